// round 8
// baseline (speedup 1.0000x reference)
#include <cuda_runtime.h>
#include <math.h>
#include <stdint.h>

// ---------------- problem constants ----------------
#define FEAT_IN 64
#define EMB 256
#define KTOP 30
#define BB 48
#define NGRAPH 11
#define GG 528            // BB*NGRAPH
#define NPG 192
#define EPG 384
#define NN 101376         // GG*NPG
#define EE 202752         // GG*EPG
#define DD 769            // 3*EMB+1
#define DPAD 776          // padded to mult of 8
#define ROWS5 (GG*KTOP)   // 15840
#define DENSE1 2816       // 11*EMB
#define EMBK (NGRAPH*DENSE1) // 30976
#define ROWS6 (GG*11)     // 5808
#define K6 640            // 5*128
#define NSPLIT 242        // 242*128 = 30976
#define KR 128

// ---------------- scratch (device globals; no cudaMalloc allowed) ----------------
__device__ float g_P  [(size_t)NN*EMB];
__device__ float g_x1 [(size_t)NN*EMB];
__device__ float g_x2 [(size_t)NN*EMB];
__device__ float g_x3 [(size_t)NN*EMB];
__device__ float g_x4 [NN];
__device__ float g_h4 [NN];
__device__ float g_dis[NN];
__device__ int   g_deg[NN];
__device__ int   g_csr_off[NN];
__device__ int   g_csr_src[EE];
__device__ float g_csr_coef[EE];
__device__ int   g_topk[ROWS5];
__device__ float g_XS [(size_t)ROWS5*DPAD];
__device__ float g_W5P[DPAD*128];
__device__ float g_Y5 [(size_t)ROWS5*128];
__device__ float g_PL [(size_t)GG*15*128];
__device__ float g_A6 [(size_t)ROWS6*K6];
__device__ float g_BW6[(size_t)K6*EMB];
__device__ float g_C6 [(size_t)ROWS6*EMB];
__device__ float g_Y6 [(size_t)GG*DENSE1];
__device__ float g_part[(size_t)NSPLIT*BB*EMB];
__device__ float g_H  [BB*EMB];
// transposed + tf32-split weights for GCN layers ([N x K] = B^T)
__device__ float g_WT1H[EMB*FEAT_IN];
__device__ float g_WT1L[EMB*FEAT_IN];
__device__ float g_WT2H[EMB*EMB];
__device__ float g_WT2L[EMB*EMB];
__device__ float g_WT3H[EMB*EMB];
__device__ float g_WT3L[EMB*EMB];

__device__ __forceinline__ uint32_t f2tf32(float x) {
    uint32_t r;
    asm("cvt.rna.tf32.f32 %0, %1;" : "=r"(r) : "f"(x));
    return r;
}

__device__ __forceinline__ void mma_tf32(float* c, const uint32_t* a, const uint32_t* b) {
    asm volatile(
        "mma.sync.aligned.m16n8k8.row.col.f32.tf32.tf32.f32 "
        "{%0,%1,%2,%3}, {%4,%5,%6,%7}, {%8,%9}, {%0,%1,%2,%3};"
        : "+f"(c[0]), "+f"(c[1]), "+f"(c[2]), "+f"(c[3])
        : "r"(a[0]), "r"(a[1]), "r"(a[2]), "r"(a[3]), "r"(b[0]), "r"(b[1]));
}

// ---------------- tf32x3 GEMM via mma.sync ----------------
#define ASTRIDE 20
__global__ __launch_bounds__(256)
void mma_gemm(const float* __restrict__ A, int lda,
              const float* __restrict__ BTh, const float* __restrict__ BTl,
              const float* __restrict__ bias, float* __restrict__ C,
              int K, int N, int act) {
    __shared__ float Ah[128][ASTRIDE], Al[128][ASTRIDE];
    __shared__ float Bh[128][ASTRIDE], Bl[128][ASTRIDE];
    int tid = threadIdx.x;
    int bm = blockIdx.y * 128, bn = blockIdx.x * 128;
    int wid = tid >> 5, lane = tid & 31;
    int warp_m = (wid & 3) * 32, warp_n = (wid >> 2) * 64;
    int grp = lane >> 2, thr = lane & 3;

    float acc[2][8][4];
    #pragma unroll
    for (int mt = 0; mt < 2; mt++)
        #pragma unroll
        for (int nt = 0; nt < 8; nt++)
            #pragma unroll
            for (int q = 0; q < 4; q++) acc[mt][nt][q] = 0.f;

    for (int k0 = 0; k0 < K; k0 += 16) {
        #pragma unroll
        for (int it = 0; it < 2; it++) {
            int idx = tid + it * 256;
            int r = idx >> 2, cq = idx & 3;
            float4 v = *(const float4*)(A + (size_t)(bm + r) * lda + k0 + cq * 4);
            float4 hi, lo;
            hi.x = __uint_as_float(f2tf32(v.x)); lo.x = __uint_as_float(f2tf32(v.x - hi.x));
            hi.y = __uint_as_float(f2tf32(v.y)); lo.y = __uint_as_float(f2tf32(v.y - hi.y));
            hi.z = __uint_as_float(f2tf32(v.z)); lo.z = __uint_as_float(f2tf32(v.z - hi.z));
            hi.w = __uint_as_float(f2tf32(v.w)); lo.w = __uint_as_float(f2tf32(v.w - hi.w));
            *(float4*)&Ah[r][cq * 4] = hi;
            *(float4*)&Al[r][cq * 4] = lo;
        }
        #pragma unroll
        for (int it = 0; it < 2; it++) {
            int idx = tid + it * 256;
            int r = idx >> 2, cq = idx & 3;
            size_t go = (size_t)(bn + r) * K + k0 + cq * 4;
            *(float4*)&Bh[r][cq * 4] = *(const float4*)(BTh + go);
            *(float4*)&Bl[r][cq * 4] = *(const float4*)(BTl + go);
        }
        __syncthreads();

        #pragma unroll
        for (int ks = 0; ks < 2; ks++) {
            int kb = ks * 8;
            uint32_t fah[2][4], fal[2][4], fbh[8][2], fbl[8][2];
            #pragma unroll
            for (int mt = 0; mt < 2; mt++) {
                int m = warp_m + mt * 16;
                fah[mt][0] = __float_as_uint(Ah[m + grp    ][kb + thr    ]);
                fah[mt][1] = __float_as_uint(Ah[m + grp + 8][kb + thr    ]);
                fah[mt][2] = __float_as_uint(Ah[m + grp    ][kb + thr + 4]);
                fah[mt][3] = __float_as_uint(Ah[m + grp + 8][kb + thr + 4]);
                fal[mt][0] = __float_as_uint(Al[m + grp    ][kb + thr    ]);
                fal[mt][1] = __float_as_uint(Al[m + grp + 8][kb + thr    ]);
                fal[mt][2] = __float_as_uint(Al[m + grp    ][kb + thr + 4]);
                fal[mt][3] = __float_as_uint(Al[m + grp + 8][kb + thr + 4]);
            }
            #pragma unroll
            for (int nt = 0; nt < 8; nt++) {
                int n = warp_n + nt * 8;
                fbh[nt][0] = __float_as_uint(Bh[n + grp][kb + thr    ]);
                fbh[nt][1] = __float_as_uint(Bh[n + grp][kb + thr + 4]);
                fbl[nt][0] = __float_as_uint(Bl[n + grp][kb + thr    ]);
                fbl[nt][1] = __float_as_uint(Bl[n + grp][kb + thr + 4]);
            }
            #pragma unroll
            for (int mt = 0; mt < 2; mt++)
                #pragma unroll
                for (int nt = 0; nt < 8; nt++) {
                    mma_tf32(acc[mt][nt], fah[mt], fbh[nt]);
                    mma_tf32(acc[mt][nt], fah[mt], fbl[nt]);
                    mma_tf32(acc[mt][nt], fal[mt], fbh[nt]);
                }
        }
        __syncthreads();
    }

    #pragma unroll
    for (int mt = 0; mt < 2; mt++) {
        #pragma unroll
        for (int nt = 0; nt < 8; nt++) {
            int col = bn + warp_n + nt * 8 + thr * 2;
            float b0 = bias[col], b1 = bias[col + 1];
            #pragma unroll
            for (int half = 0; half < 2; half++) {
                int row = bm + warp_m + mt * 16 + grp + half * 8;
                float v0 = acc[mt][nt][half * 2 + 0] + b0;
                float v1 = acc[mt][nt][half * 2 + 1] + b1;
                if (act == 1) { v0 = tanhf(v0); v1 = tanhf(v1); }
                else if (act == 2) { v0 = fmaxf(v0, 0.f); v1 = fmaxf(v1, 0.f); }
                *(float2*)(C + (size_t)row * N + col) = make_float2(v0, v1);
            }
        }
    }
}

// weight transpose + tf32 split: W[K x N] -> WTh/WTl [N x K]
__global__ void wt_split(const float* __restrict__ W, float* __restrict__ WTh,
                         float* __restrict__ WTl, int Kd, int Nd) {
    int i = blockIdx.x * blockDim.x + threadIdx.x;
    if (i >= Kd * Nd) return;
    int n = i / Kd, k = i - n * Kd;
    float w = W[(size_t)k * Nd + n];
    float hi = __uint_as_float(f2tf32(w));
    float lo = __uint_as_float(f2tf32(w - hi));
    WTh[i] = hi; WTl[i] = lo;
}

// ---------------- degree / normalization ----------------
__global__ void deg_init(int* deg) {
    int i = blockIdx.x*blockDim.x + threadIdx.x;
    if (i < NN) deg[i] = 1;  // self loop
}
__global__ void deg_count(const int* __restrict__ dst, int* deg) {
    int e = blockIdx.x*blockDim.x + threadIdx.x;
    if (e < EE) atomicAdd(&deg[dst[e]], 1);
}
__global__ void dis_kernel(const int* __restrict__ deg, float* dis) {
    int i = blockIdx.x*blockDim.x + threadIdx.x;
    if (i < NN) dis[i] = rsqrtf((float)deg[i]);
}

// ---------------- CSR build: one CTA per graph (384 threads) ----------------
__global__ __launch_bounds__(EPG)
void build_csr(const int* __restrict__ src, const int* __restrict__ dst,
               const float* __restrict__ dis) {
    __shared__ int cnt[NPG];
    __shared__ int eoff[NPG];
    int g = blockIdx.x, t = threadIdx.x;
    int ebase = g * EPG, nbase = g * NPG;
    if (t < NPG) cnt[t] = 0;
    __syncthreads();
    atomicAdd(&cnt[dst[ebase + t] - nbase], 1);
    __syncthreads();
    if (t == 0) {
        int s = 0;
        for (int i = 0; i < NPG; i++) { eoff[i] = s; s += cnt[i]; }
    }
    __syncthreads();
    if (t < NPG) {
        g_csr_off[nbase + t] = ebase + eoff[t];
        cnt[t] = 0;
    }
    __syncthreads();
    {
        int e = ebase + t;
        int s = src[e], d = dst[e];
        int dl = d - nbase;
        int p = atomicAdd(&cnt[dl], 1);
        int slot = ebase + eoff[dl] + p;
        g_csr_src[slot] = s;
        g_csr_coef[slot] = dis[s] * dis[d];
    }
}

// ---------------- GCN propagation: gather form, no atomics ----------------
// P[d] = dis[d]^2 * x[d] + sum_in coef * x[s].  One warp per node.
__global__ void gcn_gather256(const float* __restrict__ X, float* __restrict__ P,
                              const float* __restrict__ dis) {
    int node = (blockIdx.x * blockDim.x + threadIdx.x) >> 5;
    if (node >= NN) return;
    int lane = threadIdx.x & 31;
    int beg = g_csr_off[node];
    int num = g_deg[node] - 1;
    float ds = dis[node];
    float wself = ds * ds;
    #pragma unroll
    for (int half = 0; half < 2; half++) {
        int c0 = half * 128;
        const float4* xr = (const float4*)(X + (size_t)node * EMB + c0);
        float4 acc = xr[lane];
        acc.x *= wself; acc.y *= wself; acc.z *= wself; acc.w *= wself;
        for (int e = 0; e < num; e++) {
            int s = g_csr_src[beg + e];
            float cf = g_csr_coef[beg + e];
            const float4* xs = (const float4*)(X + (size_t)s * EMB + c0);
            float4 v = xs[lane];
            acc.x = fmaf(cf, v.x, acc.x);
            acc.y = fmaf(cf, v.y, acc.y);
            acc.z = fmaf(cf, v.z, acc.z);
            acc.w = fmaf(cf, v.w, acc.w);
        }
        ((float4*)(P + (size_t)node * EMB + c0))[lane] = acc;
    }
}
// C = 64: lanes cover all 64 channels via float2, 1 pass.
__global__ void gcn_gather64(const float* __restrict__ X, float* __restrict__ P,
                             const float* __restrict__ dis) {
    int node = (blockIdx.x * blockDim.x + threadIdx.x) >> 5;
    if (node >= NN) return;
    int lane = threadIdx.x & 31;
    int beg = g_csr_off[node];
    int num = g_deg[node] - 1;
    float ds = dis[node];
    float wself = ds * ds;
    const float2* xr = (const float2*)(X + (size_t)node * FEAT_IN);
    float2 acc = xr[lane];
    acc.x *= wself; acc.y *= wself;
    for (int e = 0; e < num; e++) {
        int s = g_csr_src[beg + e];
        float cf = g_csr_coef[beg + e];
        const float2* xs = (const float2*)(X + (size_t)s * FEAT_IN);
        float2 v = xs[lane];
        acc.x = fmaf(cf, v.x, acc.x);
        acc.y = fmaf(cf, v.y, acc.y);
    }
    ((float2*)(P + (size_t)node * FEAT_IN))[lane] = acc;
}

// ---------------- layer 4 (EMB -> 1) ----------------
__global__ void gemv4(const float* __restrict__ x3, const float* __restrict__ W4,
                      float* __restrict__ h4) {
    int w = (blockIdx.x*blockDim.x + threadIdx.x) >> 5;
    int lane = threadIdx.x & 31;
    if (w >= NN) return;
    const float* row = x3 + (size_t)w*EMB;
    float s = 0.f;
    #pragma unroll
    for (int i = 0; i < 8; i++) s = fmaf(row[lane + 32*i], W4[lane + 32*i], s);
    #pragma unroll
    for (int o = 16; o; o >>= 1) s += __shfl_down_sync(0xffffffffu, s, o);
    if (lane == 0) h4[w] = s;
}
// fused gather + bias + tanh for the 1-channel layer
__global__ void gather_tanh1(const float* __restrict__ h4, const float* __restrict__ dis,
                             const float* __restrict__ b4, float* __restrict__ x4) {
    int n = blockIdx.x*blockDim.x + threadIdx.x;
    if (n >= NN) return;
    float ds = dis[n];
    float acc = h4[n] * ds * ds;
    int beg = g_csr_off[n];
    int num = g_deg[n] - 1;
    for (int e = 0; e < num; e++)
        acc = fmaf(g_csr_coef[beg + e], h4[g_csr_src[beg + e]], acc);
    x4[n] = tanhf(acc + b4[0]);
}

// ---------------- generic SGEMM (conv5/conv6) ----------------
__global__ __launch_bounds__(256)
void sgemm(const float* __restrict__ A, const float* __restrict__ Bm,
           const float* __restrict__ bias, float* __restrict__ C,
           int M, int N, int K, int act) {
    __shared__ float As[8][128];
    __shared__ float Bs[8][128];
    int tid = threadIdx.x;
    int bm = blockIdx.y * 128, bn = blockIdx.x * 128;
    int tx = tid & 15, ty = tid >> 4;
    int arow = tid >> 1, acol = (tid & 1) << 2;
    int brow = tid >> 5, bcol = (tid & 31) << 2;
    float acc[8][8];
    #pragma unroll
    for (int i = 0; i < 8; i++)
        #pragma unroll
        for (int j = 0; j < 8; j++) acc[i][j] = 0.f;

    bool avalid = (bm + arow) < M;
    const float* Aptr = A + (size_t)(bm + arow)*K + acol;
    const float* Bptr = Bm + (size_t)brow*N + bn + bcol;

    for (int k0 = 0; k0 < K; k0 += 8) {
        float4 av = make_float4(0.f,0.f,0.f,0.f);
        if (avalid) av = *(const float4*)(Aptr + k0);
        As[acol+0][arow] = av.x; As[acol+1][arow] = av.y;
        As[acol+2][arow] = av.z; As[acol+3][arow] = av.w;
        float4 bv = *(const float4*)(Bptr + (size_t)k0*N);
        *(float4*)&Bs[brow][bcol] = bv;
        __syncthreads();
        #pragma unroll
        for (int kk = 0; kk < 8; kk++) {
            float ra[8], rb[8];
            *(float4*)(ra)   = *(float4*)&As[kk][ty*8];
            *(float4*)(ra+4) = *(float4*)&As[kk][ty*8+4];
            *(float4*)(rb)   = *(float4*)&Bs[kk][tx*8];
            *(float4*)(rb+4) = *(float4*)&Bs[kk][tx*8+4];
            #pragma unroll
            for (int i = 0; i < 8; i++)
                #pragma unroll
                for (int j = 0; j < 8; j++)
                    acc[i][j] = fmaf(ra[i], rb[j], acc[i][j]);
        }
        __syncthreads();
    }
    #pragma unroll
    for (int i = 0; i < 8; i++) {
        int row = bm + ty*8 + i;
        if (row >= M) continue;
        #pragma unroll
        for (int j = 0; j < 8; j++) {
            int col = bn + tx*8 + j;
            float v = acc[i][j] + bias[col];
            if (act == 1) v = tanhf(v);
            else if (act == 2) v = fmaxf(v, 0.f);
            C[(size_t)row*N + col] = v;
        }
    }
}

// ---------------- per-graph top-K ----------------
__global__ void topk_kernel(const float* __restrict__ x4, int* __restrict__ topk) {
    __shared__ float key[256];
    __shared__ int   kid[256];
    int g = blockIdx.x, t = threadIdx.x;
    if (t < NPG) { key[t] = x4[g*NPG + t]; kid[t] = t; }
    else         { key[t] = -1e30f;        kid[t] = t; }
    __syncthreads();
    for (int k = 2; k <= 256; k <<= 1) {
        for (int j = k >> 1; j > 0; j >>= 1) {
            int ixj = t ^ j;
            if (ixj > t) {
                float ka = key[t], kb = key[ixj];
                int   ia = kid[t], ib = kid[ixj];
                bool before = (ka > kb) || (ka == kb && ia < ib);
                bool up = ((t & k) == 0);
                if (up ? !before : before) {
                    key[t] = kb; key[ixj] = ka;
                    kid[t] = ib; kid[ixj] = ia;
                }
            }
            __syncthreads();
        }
    }
    if (t < KTOP) topk[g*KTOP + t] = g*NPG + kid[t];
}

// ---------------- gather selected node features ----------------
__global__ void gather_xs(const int* __restrict__ topk, float* __restrict__ XS) {
    int idx = blockIdx.x*blockDim.x + threadIdx.x;
    if (idx >= ROWS5*DPAD) return;
    int r = idx / DPAD, d = idx - r*DPAD;
    int node = topk[r];
    float v;
    if      (d < 256)  v = g_x1[(size_t)node*EMB + d];
    else if (d < 512)  v = g_x2[(size_t)node*EMB + d - 256];
    else if (d < 768)  v = g_x3[(size_t)node*EMB + d - 512];
    else if (d == 768) v = g_x4[node];
    else               v = 0.f;
    XS[idx] = v;
}

// ---------------- small packing kernels ----------------
__global__ void w5pad(const float* __restrict__ w5, float* __restrict__ W5P) {
    int idx = blockIdx.x*blockDim.x + threadIdx.x;
    if (idx >= DPAD*128) return;
    int d = idx >> 7, oc = idx & 127;
    W5P[idx] = (d < DD) ? w5[oc*DD + d] : 0.f;
}
__global__ void maxpool(const float* __restrict__ Y5, float* __restrict__ PL) {
    int idx = blockIdx.x*blockDim.x + threadIdx.x;
    if (idx >= GG*15*128) return;
    int g = idx / (15*128), rem = idx - g*15*128;
    int j = rem >> 7, ic = rem & 127;
    const float* base = Y5 + (size_t)g*KTOP*128;
    PL[idx] = fmaxf(base[(2*j)*128 + ic], base[(2*j+1)*128 + ic]);
}
__global__ void a6build(const float* __restrict__ PL, float* __restrict__ A6) {
    int idx = blockIdx.x*blockDim.x + threadIdx.x;
    if (idx >= ROWS6*K6) return;
    int r = idx / K6, q = idx - r*K6;
    int g = r / 11, t = r - g*11;
    A6[idx] = PL[(size_t)g*15*128 + t*128 + q];
}
__global__ void bw6build(const float* __restrict__ w6, float* __restrict__ BW6) {
    int idx = blockIdx.x*blockDim.x + threadIdx.x;
    if (idx >= K6*EMB) return;
    int kq = idx >> 8, oc = idx & 255;
    int dt = kq >> 7, ic = kq & 127;
    BW6[idx] = w6[oc*K6 + ic*5 + dt];
}
__global__ void reorder6(const float* __restrict__ C6, float* __restrict__ Y6) {
    int idx = blockIdx.x*blockDim.x + threadIdx.x;
    if (idx >= ROWS6*EMB) return;
    int r = idx >> 8, oc = idx & 255;
    int g = r / 11, t = r - g*11;
    Y6[(size_t)g*DENSE1 + oc*11 + t] = C6[idx];
}

// ---------------- dense1 split-K ----------------
__global__ __launch_bounds__(256) void dense1_part(const float* __restrict__ Wc1) {
    __shared__ float se[BB*KR];
    int blk = blockIdx.x;
    int k0 = blk * KR;
    int tid = threadIdx.x;
    for (int i = tid; i < BB*KR; i += 256) {
        int b = i >> 7, kk = i & 127;
        se[i] = g_Y6[(size_t)b*EMBK + k0 + kk];
    }
    __syncthreads();
    float acc[BB];
    #pragma unroll
    for (int b = 0; b < BB; b++) acc[b] = 0.f;
    int j = tid;
    for (int kk = 0; kk < KR; kk++) {
        float w = Wc1[(size_t)(k0+kk)*EMB + j];
        #pragma unroll
        for (int b = 0; b < BB; b++) acc[b] = fmaf(se[b*KR + kk], w, acc[b]);
    }
    float* out = g_part + (size_t)blk*BB*EMB;
    for (int b = 0; b < BB; b++) out[b*EMB + j] = acc[b];
}
__global__ void dense1_reduce(const float* __restrict__ bc1) {
    int i = blockIdx.x*blockDim.x + threadIdx.x;
    if (i >= BB*EMB) return;
    float s = 0.f;
    for (int sp = 0; sp < NSPLIT; sp++) s += g_part[(size_t)sp*BB*EMB + i];
    s += bc1[i & 255];
    g_H[i] = fmaxf(s, 0.f);
}
__global__ void dense2(const float* __restrict__ Wc2, const float* __restrict__ bc2,
                       float* __restrict__ out) {
    __shared__ float h[EMB];
    int b = blockIdx.x, t = threadIdx.x;
    h[t] = g_H[b*EMB + t];
    __syncthreads();
    if (t < 10) {
        float s = bc2[t];
        for (int k = 0; k < EMB; k++) s = fmaf(h[k], Wc2[k*10 + t], s);
        out[b*10 + t] = s;
    }
}

// ---------------- launch ----------------
extern "C" void kernel_launch(void* const* d_in, const int* in_sizes, int n_in,
                              void* d_out, int out_size) {
    const float* x   = (const float*)d_in[0];
    const int*   src = (const int*)d_in[1];
    const int*   dst = (const int*)d_in[2];
    const float* W1  = (const float*)d_in[3];
    const float* b1  = (const float*)d_in[4];
    const float* W2  = (const float*)d_in[5];
    const float* b2  = (const float*)d_in[6];
    const float* W3  = (const float*)d_in[7];
    const float* b3  = (const float*)d_in[8];
    const float* W4  = (const float*)d_in[9];
    const float* b4  = (const float*)d_in[10];
    const float* w5  = (const float*)d_in[11];
    const float* bc5 = (const float*)d_in[12];
    const float* w6  = (const float*)d_in[13];
    const float* bc6 = (const float*)d_in[14];
    const float* Wc1 = (const float*)d_in[15];
    const float* bc1 = (const float*)d_in[16];
    const float* Wc2 = (const float*)d_in[17];
    const float* bc2 = (const float*)d_in[18];
    float* out = (float*)d_out;

    void* p;
    cudaGetSymbolAddress(&p, g_P);    float* P   = (float*)p;
    cudaGetSymbolAddress(&p, g_x1);   float* X1  = (float*)p;
    cudaGetSymbolAddress(&p, g_x2);   float* X2  = (float*)p;
    cudaGetSymbolAddress(&p, g_x3);   float* X3  = (float*)p;
    cudaGetSymbolAddress(&p, g_x4);   float* X4  = (float*)p;
    cudaGetSymbolAddress(&p, g_h4);   float* H4  = (float*)p;
    cudaGetSymbolAddress(&p, g_dis);  float* DIS = (float*)p;
    cudaGetSymbolAddress(&p, g_deg);  int*   DEG = (int*)p;
    cudaGetSymbolAddress(&p, g_topk); int*   TK  = (int*)p;
    cudaGetSymbolAddress(&p, g_XS);   float* XS  = (float*)p;
    cudaGetSymbolAddress(&p, g_W5P);  float* W5P = (float*)p;
    cudaGetSymbolAddress(&p, g_Y5);   float* Y5  = (float*)p;
    cudaGetSymbolAddress(&p, g_PL);   float* PL  = (float*)p;
    cudaGetSymbolAddress(&p, g_A6);   float* A6  = (float*)p;
    cudaGetSymbolAddress(&p, g_BW6);  float* BW6 = (float*)p;
    cudaGetSymbolAddress(&p, g_C6);   float* C6  = (float*)p;
    cudaGetSymbolAddress(&p, g_Y6);   float* Y6  = (float*)p;
    cudaGetSymbolAddress(&p, g_WT1H); float* WT1H = (float*)p;
    cudaGetSymbolAddress(&p, g_WT1L); float* WT1L = (float*)p;
    cudaGetSymbolAddress(&p, g_WT2H); float* WT2H = (float*)p;
    cudaGetSymbolAddress(&p, g_WT2L); float* WT2L = (float*)p;
    cudaGetSymbolAddress(&p, g_WT3H); float* WT3H = (float*)p;
    cudaGetSymbolAddress(&p, g_WT3L); float* WT3L = (float*)p;

    const int T = 256;

    // degree / norm / CSR (fixed graph structure)
    deg_init<<<(NN+T-1)/T, T>>>(DEG);
    deg_count<<<(EE+T-1)/T, T>>>(dst, DEG);
    dis_kernel<<<(NN+T-1)/T, T>>>(DEG, DIS);
    build_csr<<<GG, EPG>>>(src, dst, DIS);

    // weight transpose + tf32 split
    wt_split<<<(FEAT_IN*EMB+T-1)/T, T>>>(W1, WT1H, WT1L, FEAT_IN, EMB);
    wt_split<<<(EMB*EMB+T-1)/T, T>>>(W2, WT2H, WT2L, EMB, EMB);
    wt_split<<<(EMB*EMB+T-1)/T, T>>>(W3, WT3H, WT3L, EMB, EMB);

    dim3 gL(2, NN/128);
    const int GW = (NN*32 + T - 1) / T;   // warp-per-node grid

    // layer 1: P = Â x (gather, no atomics), x1 = tanh(P@W1 + b1)
    gcn_gather64<<<GW, T>>>(x, P, DIS);
    mma_gemm<<<gL, 256>>>(P, FEAT_IN, WT1H, WT1L, b1, X1, FEAT_IN, EMB, 1);

    // layer 2
    gcn_gather256<<<GW, T>>>(X1, P, DIS);
    mma_gemm<<<gL, 256>>>(P, EMB, WT2H, WT2L, b2, X2, EMB, EMB, 1);

    // layer 3
    gcn_gather256<<<GW, T>>>(X2, P, DIS);
    mma_gemm<<<gL, 256>>>(P, EMB, WT3H, WT3L, b3, X3, EMB, EMB, 1);

    // layer 4: h4 = x3@W4; x4 = tanh(Â h4 + b4)  (fused gather)
    gemv4<<<(NN+7)/8, T>>>(X3, W4, H4);
    gather_tanh1<<<(NN+T-1)/T, T>>>(H4, DIS, b4, X4);

    // sort-pool + gather
    topk_kernel<<<GG, 256>>>(X4, TK);
    gather_xs<<<(ROWS5*DPAD+T-1)/T, T>>>(TK, XS);

    // conv5 as GEMM
    w5pad<<<(DPAD*128+T-1)/T, T>>>(w5, W5P);
    sgemm<<<dim3(1, (ROWS5+127)/128), T>>>(XS, W5P, bc5, Y5, ROWS5, 128, DPAD, 2);

    // maxpool(2,2)
    maxpool<<<(GG*15*128+T-1)/T, T>>>(Y5, PL);

    // conv6 as GEMM
    a6build<<<(ROWS6*K6+T-1)/T, T>>>(PL, A6);
    bw6build<<<(K6*EMB+T-1)/T, T>>>(w6, BW6);
    sgemm<<<dim3(2, (ROWS6+127)/128), T>>>(A6, BW6, bc6, C6, ROWS6, EMB, K6, 2);
    reorder6<<<(ROWS6*EMB+T-1)/T, T>>>(C6, Y6);

    // dense layers
    dense1_part<<<NSPLIT, 256>>>(Wc1);
    dense1_reduce<<<(BB*EMB+T-1)/T, T>>>(bc1);
    dense2<<<BB, 256>>>(Wc2, bc2, out);
}

// round 13
// speedup vs baseline: 1.3900x; 1.3900x over previous
#include <cuda_runtime.h>
#include <math.h>
#include <stdint.h>

// ---------------- problem constants ----------------
#define FEAT_IN 64
#define EMB 256
#define KTOP 30
#define BB 48
#define NGRAPH 11
#define GG 528            // BB*NGRAPH
#define NPG 192
#define NN 101376         // GG*NPG
#define EE 202752         // GG*384
#define DD 769            // 3*EMB+1
#define DPAD 776          // padded to mult of 8
#define ROWS5 (GG*KTOP)   // 15840
#define DENSE1 2816       // 11*EMB
#define EMBK (NGRAPH*DENSE1) // 30976
#define ROWS6 (GG*11)     // 5808
#define K6 640            // 5*128
#define NSPLIT 242        // 242*128 = 30976
#define KR 128

// ---------------- scratch (device globals; no cudaMalloc allowed) ----------------
__device__ float g_P  [(size_t)NN*EMB];
__device__ float g_P2 [(size_t)NN*EMB];
__device__ float g_x1 [(size_t)NN*EMB];
__device__ float g_x2 [(size_t)NN*EMB];
__device__ float g_x3 [(size_t)NN*EMB];
__device__ float g_x4 [NN];
__device__ float g_h4 [NN];
__device__ float g_dis[NN];
__device__ int   g_deg[NN];
__device__ int   g_topk[ROWS5];
__device__ float g_XS [(size_t)ROWS5*DPAD];
__device__ float g_W5P[DPAD*128];
__device__ float g_Y5 [(size_t)ROWS5*128];
__device__ float g_PL [(size_t)GG*15*128];
__device__ float g_A6 [(size_t)ROWS6*K6];
__device__ float g_BW6[(size_t)K6*EMB];
__device__ float g_C6 [(size_t)ROWS6*EMB];
__device__ float g_Y6 [(size_t)GG*DENSE1];
__device__ float g_part[(size_t)NSPLIT*BB*EMB];
__device__ float g_H  [BB*EMB];
// transposed + tf32-split weights for GCN layers ([N x K] = B^T)
__device__ float g_WT1H[EMB*FEAT_IN];
__device__ float g_WT1L[EMB*FEAT_IN];
__device__ float g_WT2H[EMB*EMB];
__device__ float g_WT2L[EMB*EMB];
__device__ float g_WT3H[EMB*EMB];
__device__ float g_WT3L[EMB*EMB];

__device__ __forceinline__ uint32_t f2tf32(float x) {
    uint32_t r;
    asm("cvt.rna.tf32.f32 %0, %1;" : "=r"(r) : "f"(x));
    return r;
}

__device__ __forceinline__ void mma_tf32(float* c, const uint32_t* a, const uint32_t* b) {
    asm volatile(
        "mma.sync.aligned.m16n8k8.row.col.f32.tf32.tf32.f32 "
        "{%0,%1,%2,%3}, {%4,%5,%6,%7}, {%8,%9}, {%0,%1,%2,%3};"
        : "+f"(c[0]), "+f"(c[1]), "+f"(c[2]), "+f"(c[3])
        : "r"(a[0]), "r"(a[1]), "r"(a[2]), "r"(a[3]), "r"(b[0]), "r"(b[1]));
}

// ---------------- tf32x3 GEMM via mma.sync: C[M x N] = act(A @ BT^T + bias)
// Optionally also writes Pout[row][col] = C[row][col] * dis[row]^2  (fused
// prop_init for the NEXT GCN layer; Pout must differ from A's buffer).
#define ASTRIDE 20
__global__ __launch_bounds__(256)
void mma_gemm(const float* __restrict__ A, int lda,
              const float* __restrict__ BTh, const float* __restrict__ BTl,
              const float* __restrict__ bias, float* __restrict__ C,
              int K, int N, int act,
              float* __restrict__ Pout, const float* __restrict__ dis) {
    __shared__ float Ah[128][ASTRIDE], Al[128][ASTRIDE];
    __shared__ float Bh[128][ASTRIDE], Bl[128][ASTRIDE];
    int tid = threadIdx.x;
    int bm = blockIdx.y * 128, bn = blockIdx.x * 128;
    int wid = tid >> 5, lane = tid & 31;
    int warp_m = (wid & 3) * 32, warp_n = (wid >> 2) * 64;
    int grp = lane >> 2, thr = lane & 3;

    float acc[2][8][4];
    #pragma unroll
    for (int mt = 0; mt < 2; mt++)
        #pragma unroll
        for (int nt = 0; nt < 8; nt++)
            #pragma unroll
            for (int q = 0; q < 4; q++) acc[mt][nt][q] = 0.f;

    for (int k0 = 0; k0 < K; k0 += 16) {
        #pragma unroll
        for (int it = 0; it < 2; it++) {
            int idx = tid + it * 256;
            int r = idx >> 2, cq = idx & 3;
            float4 v = *(const float4*)(A + (size_t)(bm + r) * lda + k0 + cq * 4);
            float4 hi, lo;
            hi.x = __uint_as_float(f2tf32(v.x)); lo.x = __uint_as_float(f2tf32(v.x - hi.x));
            hi.y = __uint_as_float(f2tf32(v.y)); lo.y = __uint_as_float(f2tf32(v.y - hi.y));
            hi.z = __uint_as_float(f2tf32(v.z)); lo.z = __uint_as_float(f2tf32(v.z - hi.z));
            hi.w = __uint_as_float(f2tf32(v.w)); lo.w = __uint_as_float(f2tf32(v.w - hi.w));
            *(float4*)&Ah[r][cq * 4] = hi;
            *(float4*)&Al[r][cq * 4] = lo;
        }
        #pragma unroll
        for (int it = 0; it < 2; it++) {
            int idx = tid + it * 256;
            int r = idx >> 2, cq = idx & 3;
            size_t go = (size_t)(bn + r) * K + k0 + cq * 4;
            *(float4*)&Bh[r][cq * 4] = *(const float4*)(BTh + go);
            *(float4*)&Bl[r][cq * 4] = *(const float4*)(BTl + go);
        }
        __syncthreads();

        #pragma unroll
        for (int ks = 0; ks < 2; ks++) {
            int kb = ks * 8;
            uint32_t fah[2][4], fal[2][4], fbh[8][2], fbl[8][2];
            #pragma unroll
            for (int mt = 0; mt < 2; mt++) {
                int m = warp_m + mt * 16;
                fah[mt][0] = __float_as_uint(Ah[m + grp    ][kb + thr    ]);
                fah[mt][1] = __float_as_uint(Ah[m + grp + 8][kb + thr    ]);
                fah[mt][2] = __float_as_uint(Ah[m + grp    ][kb + thr + 4]);
                fah[mt][3] = __float_as_uint(Ah[m + grp + 8][kb + thr + 4]);
                fal[mt][0] = __float_as_uint(Al[m + grp    ][kb + thr    ]);
                fal[mt][1] = __float_as_uint(Al[m + grp + 8][kb + thr    ]);
                fal[mt][2] = __float_as_uint(Al[m + grp    ][kb + thr + 4]);
                fal[mt][3] = __float_as_uint(Al[m + grp + 8][kb + thr + 4]);
            }
            #pragma unroll
            for (int nt = 0; nt < 8; nt++) {
                int n = warp_n + nt * 8;
                fbh[nt][0] = __float_as_uint(Bh[n + grp][kb + thr    ]);
                fbh[nt][1] = __float_as_uint(Bh[n + grp][kb + thr + 4]);
                fbl[nt][0] = __float_as_uint(Bl[n + grp][kb + thr    ]);
                fbl[nt][1] = __float_as_uint(Bl[n + grp][kb + thr + 4]);
            }
            #pragma unroll
            for (int mt = 0; mt < 2; mt++)
                #pragma unroll
                for (int nt = 0; nt < 8; nt++) {
                    mma_tf32(acc[mt][nt], fah[mt], fbh[nt]);
                    mma_tf32(acc[mt][nt], fah[mt], fbl[nt]);
                    mma_tf32(acc[mt][nt], fal[mt], fbh[nt]);
                }
        }
        __syncthreads();
    }

    // epilogue (+ optional fused prop_init for next layer)
    #pragma unroll
    for (int mt = 0; mt < 2; mt++) {
        #pragma unroll
        for (int nt = 0; nt < 8; nt++) {
            int col = bn + warp_n + nt * 8 + thr * 2;
            float b0 = bias[col], b1 = bias[col + 1];
            #pragma unroll
            for (int half = 0; half < 2; half++) {
                int row = bm + warp_m + mt * 16 + grp + half * 8;
                float v0 = acc[mt][nt][half * 2 + 0] + b0;
                float v1 = acc[mt][nt][half * 2 + 1] + b1;
                if (act == 1) { v0 = tanhf(v0); v1 = tanhf(v1); }
                else if (act == 2) { v0 = fmaxf(v0, 0.f); v1 = fmaxf(v1, 0.f); }
                *(float2*)(C + (size_t)row * N + col) = make_float2(v0, v1);
                if (Pout) {
                    float ds = dis[row];
                    float ws = ds * ds;
                    *(float2*)(Pout + (size_t)row * N + col) = make_float2(v0 * ws, v1 * ws);
                }
            }
        }
    }
}

// weight transpose + tf32 split: W[K x N] -> WTh/WTl [N x K]
__global__ void wt_split(const float* __restrict__ W, float* __restrict__ WTh,
                         float* __restrict__ WTl, int Kd, int Nd) {
    int i = blockIdx.x * blockDim.x + threadIdx.x;
    if (i >= Kd * Nd) return;
    int n = i / Kd, k = i - n * Kd;
    float w = W[(size_t)k * Nd + n];
    float hi = __uint_as_float(f2tf32(w));
    float lo = __uint_as_float(f2tf32(w - hi));
    WTh[i] = hi; WTl[i] = lo;
}

// ---------------- degree / normalization ----------------
__global__ void deg_init(int* deg) {
    int i = blockIdx.x*blockDim.x + threadIdx.x;
    if (i < NN) deg[i] = 1;  // self loop
}
__global__ void deg_count(const int* __restrict__ dst, int* deg) {
    int e = blockIdx.x*blockDim.x + threadIdx.x;
    if (e < EE) atomicAdd(&deg[dst[e]], 1);
}
__global__ void dis_kernel(const int* __restrict__ deg, float* dis) {
    int i = blockIdx.x*blockDim.x + threadIdx.x;
    if (i < NN) dis[i] = rsqrtf((float)deg[i]);
}

// ---------------- propagation P = Â X (scatter form) ----------------
__global__ void prop_init(const float* __restrict__ X, float* __restrict__ P,
                          const float* __restrict__ dis, int C, int total) {
    int i = blockIdx.x*blockDim.x + threadIdx.x;
    if (i >= total) return;
    int n = i / C;
    float s = dis[n];
    P[i] = X[i] * s * s;
}
__global__ void prop_scatter(const float* __restrict__ X, float* __restrict__ P,
                             const int* __restrict__ src, const int* __restrict__ dst,
                             const float* __restrict__ dis, int C) {
    int e = blockIdx.x*(blockDim.x>>5) + (threadIdx.x>>5);
    if (e >= EE) return;
    int lane = threadIdx.x & 31;
    int s = src[e], d = dst[e];
    float coef = dis[s]*dis[d];
    const float* xs = X + (size_t)s*C;
    float* pd = P + (size_t)d*C;
    for (int c = lane; c < C; c += 32)
        atomicAdd(pd + c, xs[c]*coef);
}

// ---------------- generic SGEMM (conv5/conv6) ----------------
__global__ __launch_bounds__(256)
void sgemm(const float* __restrict__ A, const float* __restrict__ Bm,
           const float* __restrict__ bias, float* __restrict__ C,
           int M, int N, int K, int act) {
    __shared__ float As[8][128];
    __shared__ float Bs[8][128];
    int tid = threadIdx.x;
    int bm = blockIdx.y * 128, bn = blockIdx.x * 128;
    int tx = tid & 15, ty = tid >> 4;
    int arow = tid >> 1, acol = (tid & 1) << 2;
    int brow = tid >> 5, bcol = (tid & 31) << 2;
    float acc[8][8];
    #pragma unroll
    for (int i = 0; i < 8; i++)
        #pragma unroll
        for (int j = 0; j < 8; j++) acc[i][j] = 0.f;

    bool avalid = (bm + arow) < M;
    const float* Aptr = A + (size_t)(bm + arow)*K + acol;
    const float* Bptr = Bm + (size_t)brow*N + bn + bcol;

    for (int k0 = 0; k0 < K; k0 += 8) {
        float4 av = make_float4(0.f,0.f,0.f,0.f);
        if (avalid) av = *(const float4*)(Aptr + k0);
        As[acol+0][arow] = av.x; As[acol+1][arow] = av.y;
        As[acol+2][arow] = av.z; As[acol+3][arow] = av.w;
        float4 bv = *(const float4*)(Bptr + (size_t)k0*N);
        *(float4*)&Bs[brow][bcol] = bv;
        __syncthreads();
        #pragma unroll
        for (int kk = 0; kk < 8; kk++) {
            float ra[8], rb[8];
            *(float4*)(ra)   = *(float4*)&As[kk][ty*8];
            *(float4*)(ra+4) = *(float4*)&As[kk][ty*8+4];
            *(float4*)(rb)   = *(float4*)&Bs[kk][tx*8];
            *(float4*)(rb+4) = *(float4*)&Bs[kk][tx*8+4];
            #pragma unroll
            for (int i = 0; i < 8; i++)
                #pragma unroll
                for (int j = 0; j < 8; j++)
                    acc[i][j] = fmaf(ra[i], rb[j], acc[i][j]);
        }
        __syncthreads();
    }
    #pragma unroll
    for (int i = 0; i < 8; i++) {
        int row = bm + ty*8 + i;
        if (row >= M) continue;
        #pragma unroll
        for (int j = 0; j < 8; j++) {
            int col = bn + tx*8 + j;
            float v = acc[i][j] + bias[col];
            if (act == 1) v = tanhf(v);
            else if (act == 2) v = fmaxf(v, 0.f);
            C[(size_t)row*N + col] = v;
        }
    }
}

// ---------------- layer 4 (EMB -> 1) ----------------
__global__ void gemv4(const float* __restrict__ x3, const float* __restrict__ W4,
                      float* __restrict__ h4) {
    int w = (blockIdx.x*blockDim.x + threadIdx.x) >> 5;
    int lane = threadIdx.x & 31;
    if (w >= NN) return;
    const float* row = x3 + (size_t)w*EMB;
    float s = 0.f;
    #pragma unroll
    for (int i = 0; i < 8; i++) s = fmaf(row[lane + 32*i], W4[lane + 32*i], s);
    #pragma unroll
    for (int o = 16; o; o >>= 1) s += __shfl_down_sync(0xffffffffu, s, o);
    if (lane == 0) h4[w] = s;
}
__global__ void init1(const float* __restrict__ h4, float* __restrict__ P4,
                      const float* __restrict__ dis) {
    int i = blockIdx.x*blockDim.x + threadIdx.x;
    if (i < NN) { float s = dis[i]; P4[i] = h4[i]*s*s; }
}
__global__ void scatter1(const float* __restrict__ h4, float* __restrict__ P4,
                         const int* __restrict__ src, const int* __restrict__ dst,
                         const float* __restrict__ dis) {
    int e = blockIdx.x*blockDim.x + threadIdx.x;
    if (e >= EE) return;
    int s = src[e], d = dst[e];
    atomicAdd(&P4[d], h4[s]*dis[s]*dis[d]);
}
__global__ void tanh4(const float* __restrict__ P4, const float* __restrict__ b4,
                      float* __restrict__ x4) {
    int i = blockIdx.x*blockDim.x + threadIdx.x;
    if (i < NN) x4[i] = tanhf(P4[i] + b4[0]);
}

// ---------------- per-graph top-K ----------------
__global__ void topk_kernel(const float* __restrict__ x4, int* __restrict__ topk) {
    __shared__ float key[256];
    __shared__ int   kid[256];
    int g = blockIdx.x, t = threadIdx.x;
    if (t < NPG) { key[t] = x4[g*NPG + t]; kid[t] = t; }
    else         { key[t] = -1e30f;        kid[t] = t; }
    __syncthreads();
    for (int k = 2; k <= 256; k <<= 1) {
        for (int j = k >> 1; j > 0; j >>= 1) {
            int ixj = t ^ j;
            if (ixj > t) {
                float ka = key[t], kb = key[ixj];
                int   ia = kid[t], ib = kid[ixj];
                bool before = (ka > kb) || (ka == kb && ia < ib);
                bool up = ((t & k) == 0);
                if (up ? !before : before) {
                    key[t] = kb; key[ixj] = ka;
                    kid[t] = ib; kid[ixj] = ia;
                }
            }
            __syncthreads();
        }
    }
    if (t < KTOP) topk[g*KTOP + t] = g*NPG + kid[t];
}

// ---------------- gather selected node features ----------------
__global__ void gather_xs(const int* __restrict__ topk, float* __restrict__ XS) {
    int idx = blockIdx.x*blockDim.x + threadIdx.x;
    if (idx >= ROWS5*DPAD) return;
    int r = idx / DPAD, d = idx - r*DPAD;
    int node = topk[r];
    float v;
    if      (d < 256)  v = g_x1[(size_t)node*EMB + d];
    else if (d < 512)  v = g_x2[(size_t)node*EMB + d - 256];
    else if (d < 768)  v = g_x3[(size_t)node*EMB + d - 512];
    else if (d == 768) v = g_x4[node];
    else               v = 0.f;
    XS[idx] = v;
}

// ---------------- small packing kernels ----------------
__global__ void w5pad(const float* __restrict__ w5, float* __restrict__ W5P) {
    int idx = blockIdx.x*blockDim.x + threadIdx.x;
    if (idx >= DPAD*128) return;
    int d = idx >> 7, oc = idx & 127;
    W5P[idx] = (d < DD) ? w5[oc*DD + d] : 0.f;
}
__global__ void maxpool(const float* __restrict__ Y5, float* __restrict__ PL) {
    int idx = blockIdx.x*blockDim.x + threadIdx.x;
    if (idx >= GG*15*128) return;
    int g = idx / (15*128), rem = idx - g*15*128;
    int j = rem >> 7, ic = rem & 127;
    const float* base = Y5 + (size_t)g*KTOP*128;
    PL[idx] = fmaxf(base[(2*j)*128 + ic], base[(2*j+1)*128 + ic]);
}
__global__ void a6build(const float* __restrict__ PL, float* __restrict__ A6) {
    int idx = blockIdx.x*blockDim.x + threadIdx.x;
    if (idx >= ROWS6*K6) return;
    int r = idx / K6, q = idx - r*K6;
    int g = r / 11, t = r - g*11;
    A6[idx] = PL[(size_t)g*15*128 + t*128 + q];
}
__global__ void bw6build(const float* __restrict__ w6, float* __restrict__ BW6) {
    int idx = blockIdx.x*blockDim.x + threadIdx.x;
    if (idx >= K6*EMB) return;
    int kq = idx >> 8, oc = idx & 255;
    int dt = kq >> 7, ic = kq & 127;
    BW6[idx] = w6[oc*K6 + ic*5 + dt];
}
__global__ void reorder6(const float* __restrict__ C6, float* __restrict__ Y6) {
    int idx = blockIdx.x*blockDim.x + threadIdx.x;
    if (idx >= ROWS6*EMB) return;
    int r = idx >> 8, oc = idx & 255;
    int g = r / 11, t = r - g*11;
    Y6[(size_t)g*DENSE1 + oc*11 + t] = C6[idx];
}

// ---------------- dense1 split-K ----------------
__global__ __launch_bounds__(256) void dense1_part(const float* __restrict__ Wc1) {
    __shared__ float se[BB*KR];
    int blk = blockIdx.x;
    int k0 = blk * KR;
    int tid = threadIdx.x;
    for (int i = tid; i < BB*KR; i += 256) {
        int b = i >> 7, kk = i & 127;
        se[i] = g_Y6[(size_t)b*EMBK + k0 + kk];
    }
    __syncthreads();
    float acc[BB];
    #pragma unroll
    for (int b = 0; b < BB; b++) acc[b] = 0.f;
    int j = tid;
    for (int kk = 0; kk < KR; kk++) {
        float w = Wc1[(size_t)(k0+kk)*EMB + j];
        #pragma unroll
        for (int b = 0; b < BB; b++) acc[b] = fmaf(se[b*KR + kk], w, acc[b]);
    }
    float* out = g_part + (size_t)blk*BB*EMB;
    for (int b = 0; b < BB; b++) out[b*EMB + j] = acc[b];
}
__global__ void dense1_reduce(const float* __restrict__ bc1) {
    int i = blockIdx.x*blockDim.x + threadIdx.x;
    if (i >= BB*EMB) return;
    float s = 0.f;
    for (int sp = 0; sp < NSPLIT; sp++) s += g_part[(size_t)sp*BB*EMB + i];
    s += bc1[i & 255];
    g_H[i] = fmaxf(s, 0.f);
}
__global__ void dense2(const float* __restrict__ Wc2, const float* __restrict__ bc2,
                       float* __restrict__ out) {
    __shared__ float h[EMB];
    int b = blockIdx.x, t = threadIdx.x;
    h[t] = g_H[b*EMB + t];
    __syncthreads();
    if (t < 10) {
        float s = bc2[t];
        for (int k = 0; k < EMB; k++) s = fmaf(h[k], Wc2[k*10 + t], s);
        out[b*10 + t] = s;
    }
}

// ---------------- launch ----------------
extern "C" void kernel_launch(void* const* d_in, const int* in_sizes, int n_in,
                              void* d_out, int out_size) {
    const float* x   = (const float*)d_in[0];
    const int*   src = (const int*)d_in[1];
    const int*   dst = (const int*)d_in[2];
    const float* W1  = (const float*)d_in[3];
    const float* b1  = (const float*)d_in[4];
    const float* W2  = (const float*)d_in[5];
    const float* b2  = (const float*)d_in[6];
    const float* W3  = (const float*)d_in[7];
    const float* b3  = (const float*)d_in[8];
    const float* W4  = (const float*)d_in[9];
    const float* b4  = (const float*)d_in[10];
    const float* w5  = (const float*)d_in[11];
    const float* bc5 = (const float*)d_in[12];
    const float* w6  = (const float*)d_in[13];
    const float* bc6 = (const float*)d_in[14];
    const float* Wc1 = (const float*)d_in[15];
    const float* bc1 = (const float*)d_in[16];
    const float* Wc2 = (const float*)d_in[17];
    const float* bc2 = (const float*)d_in[18];
    float* out = (float*)d_out;

    void* p;
    cudaGetSymbolAddress(&p, g_P);    float* P   = (float*)p;
    cudaGetSymbolAddress(&p, g_P2);   float* P2  = (float*)p;
    cudaGetSymbolAddress(&p, g_x1);   float* X1  = (float*)p;
    cudaGetSymbolAddress(&p, g_x2);   float* X2  = (float*)p;
    cudaGetSymbolAddress(&p, g_x3);   float* X3  = (float*)p;
    cudaGetSymbolAddress(&p, g_x4);   float* X4  = (float*)p;
    cudaGetSymbolAddress(&p, g_h4);   float* H4  = (float*)p;
    cudaGetSymbolAddress(&p, g_dis);  float* DIS = (float*)p;
    cudaGetSymbolAddress(&p, g_deg);  int*   DEG = (int*)p;
    cudaGetSymbolAddress(&p, g_topk); int*   TK  = (int*)p;
    cudaGetSymbolAddress(&p, g_XS);   float* XS  = (float*)p;
    cudaGetSymbolAddress(&p, g_W5P);  float* W5P = (float*)p;
    cudaGetSymbolAddress(&p, g_Y5);   float* Y5  = (float*)p;
    cudaGetSymbolAddress(&p, g_PL);   float* PL  = (float*)p;
    cudaGetSymbolAddress(&p, g_A6);   float* A6  = (float*)p;
    cudaGetSymbolAddress(&p, g_BW6);  float* BW6 = (float*)p;
    cudaGetSymbolAddress(&p, g_C6);   float* C6  = (float*)p;
    cudaGetSymbolAddress(&p, g_Y6);   float* Y6  = (float*)p;
    cudaGetSymbolAddress(&p, g_WT1H); float* WT1H = (float*)p;
    cudaGetSymbolAddress(&p, g_WT1L); float* WT1L = (float*)p;
    cudaGetSymbolAddress(&p, g_WT2H); float* WT2H = (float*)p;
    cudaGetSymbolAddress(&p, g_WT2L); float* WT2L = (float*)p;
    cudaGetSymbolAddress(&p, g_WT3H); float* WT3H = (float*)p;
    cudaGetSymbolAddress(&p, g_WT3L); float* WT3L = (float*)p;

    const int T = 256;

    // degree / norm
    deg_init<<<(NN+T-1)/T, T>>>(DEG);
    deg_count<<<(EE+T-1)/T, T>>>(dst, DEG);
    dis_kernel<<<(NN+T-1)/T, T>>>(DEG, DIS);

    // weight transpose + tf32 split
    wt_split<<<(FEAT_IN*EMB+T-1)/T, T>>>(W1, WT1H, WT1L, FEAT_IN, EMB);
    wt_split<<<(EMB*EMB+T-1)/T, T>>>(W2, WT2H, WT2L, EMB, EMB);
    wt_split<<<(EMB*EMB+T-1)/T, T>>>(W3, WT3H, WT3L, EMB, EMB);

    dim3 gL(2, NN/128);  // N=256 split across 2 CTAs in x

    // layer 1: P = Â x ; X1 = tanh(P@W1+b1), fused P2 = X1*dis^2
    prop_init<<<(NN*FEAT_IN+T-1)/T, T>>>(x, P, DIS, FEAT_IN, NN*FEAT_IN);
    prop_scatter<<<(EE+7)/8, T>>>(x, P, src, dst, DIS, FEAT_IN);
    mma_gemm<<<gL, 256>>>(P, FEAT_IN, WT1H, WT1L, b1, X1, FEAT_IN, EMB, 1, P2, DIS);

    // layer 2: scatter into pre-initialized P2; X2 = tanh(P2@W2+b2), fused P = X2*dis^2
    prop_scatter<<<(EE+7)/8, T>>>(X1, P2, src, dst, DIS, EMB);
    mma_gemm<<<gL, 256>>>(P2, EMB, WT2H, WT2L, b2, X2, EMB, EMB, 1, P, DIS);

    // layer 3: scatter into pre-initialized P; X3 = tanh(P@W3+b3)
    prop_scatter<<<(EE+7)/8, T>>>(X2, P, src, dst, DIS, EMB);
    mma_gemm<<<gL, 256>>>(P, EMB, WT3H, WT3L, b3, X3, EMB, EMB, 1, (float*)0, DIS);

    // layer 4
    gemv4<<<(NN+7)/8, T>>>(X3, W4, H4);
    init1<<<(NN+T-1)/T, T>>>(H4, P2, DIS);
    scatter1<<<(EE+T-1)/T, T>>>(H4, P2, src, dst, DIS);
    tanh4<<<(NN+T-1)/T, T>>>(P2, b4, X4);

    // sort-pool + gather
    topk_kernel<<<GG, 256>>>(X4, TK);
    gather_xs<<<(ROWS5*DPAD+T-1)/T, T>>>(TK, XS);

    // conv5 as GEMM
    w5pad<<<(DPAD*128+T-1)/T, T>>>(w5, W5P);
    sgemm<<<dim3(1, (ROWS5+127)/128), T>>>(XS, W5P, bc5, Y5, ROWS5, 128, DPAD, 2);

    // maxpool(2,2)
    maxpool<<<(GG*15*128+T-1)/T, T>>>(Y5, PL);

    // conv6 as GEMM
    a6build<<<(ROWS6*K6+T-1)/T, T>>>(PL, A6);
    bw6build<<<(K6*EMB+T-1)/T, T>>>(w6, BW6);
    sgemm<<<dim3(2, (ROWS6+127)/128), T>>>(A6, BW6, bc6, C6, ROWS6, EMB, K6, 2);
    reorder6<<<(ROWS6*EMB+T-1)/T, T>>>(C6, Y6);

    // dense layers
    dense1_part<<<NSPLIT, 256>>>(Wc1);
    dense1_reduce<<<(BB*EMB+T-1)/T, T>>>(bc1);
    dense2<<<BB, 256>>>(Wc2, bc2, out);
}